// round 1
// baseline (speedup 1.0000x reference)
#include <cuda_runtime.h>
#include <math.h>

// Problem constants
#define BB 8
#define CW 32      // width (channels)
#define HH 64
#define WW 64
#define TT 32
#define NM 2048    // 16*16*8 kept modes

// ---------------- scratch (device globals; no allocation) ----------------
__device__ float  g_buf0[BB*CW*HH*WW*TT];          // 134MB
__device__ float  g_buf1[BB*CW*HH*WW*TT];          // 134MB
__device__ float2 g_AZ[BB*CW*HH*WW*8];             // 67MB  (fwd-T out / inv-W out)
__device__ float2 g_BY[BB*CW*HH*16*8];             // 16.8MB (fwd-W out / inv-H out)
__device__ float2 g_xf[BB*CW*NM];                  // 4.2MB
__device__ float2 g_yf[BB*CW*NM];                  // 4.2MB
__device__ float2 g_twTf[8*32];                    // e^{-2pi i k t/32}
__device__ float2 g_twF64[16*64];                  // e^{-2pi i f(ki) n/64}
__device__ float2 g_twI64[64*16];                  // e^{+2pi i f(ki) n/64}
__device__ float2 g_twTi[32*8];                    // scaled inverse-T twiddles

__device__ __forceinline__ float gelu_f(float v){
    return 0.5f*v*(1.0f + erff(v*0.7071067811865476f));
}

// ---------------- twiddle init ----------------
__global__ void k_init_tw(){
    const double PI = 3.14159265358979323846;
    int tid = threadIdx.x;
    for(int idx=tid; idx<8*32; idx+=256){
        int k=idx/32, t=idx%32;
        double a = -2.0*PI*(double)(k*t)/32.0;
        g_twTf[idx] = make_float2((float)cos(a),(float)sin(a));
    }
    for(int idx=tid; idx<16*64; idx+=256){
        int ki=idx/64, n=idx%64;
        int f = ki<8 ? ki : ki+48;
        double a = -2.0*PI*(double)(f*n)/64.0;
        g_twF64[idx] = make_float2((float)cos(a),(float)sin(a));
    }
    for(int idx=tid; idx<64*16; idx+=256){
        int n=idx/16, ki=idx%16;
        int f = ki<8 ? ki : ki+48;
        double a = 2.0*PI*(double)(f*n)/64.0;
        g_twI64[idx] = make_float2((float)cos(a),(float)sin(a));
    }
    for(int idx=tid; idx<32*8; idx+=256){
        int t=idx/8, k=idx%8;
        double sc = (k==0 ? 1.0 : 2.0)/131072.0;   // 1/(64*64*32), Hermitian doubling
        double a = 2.0*PI*(double)(k*t)/32.0;
        g_twTi[idx] = make_float2((float)(sc*cos(a)),(float)(sc*sin(a)));
    }
}

// ---------------- head: lift (x_t broadcast + grid) -> width channels ----------------
__global__ void k_head(const float* __restrict__ xt, const float* __restrict__ pw,
                       const float* __restrict__ pb, float* __restrict__ out){
    int p = blockIdx.x*blockDim.x + threadIdx.x;   // over (b,c,h,w): 1,048,576
    int w = p & 63, h = (p>>6)&63, c = (p>>12)&31, b = p>>17;
    float base = pb[c];
    #pragma unroll
    for(int j=0;j<3;j++) base = fmaf(pw[c*6+j], xt[((b*3+j)*64+h)*64+w], base);
    base = fmaf(pw[c*6+3], (float)h*(1.0f/63.0f), base);
    base = fmaf(pw[c*6+4], (float)w*(1.0f/63.0f), base);
    float ct = pw[c*6+5]*(1.0f/31.0f);
    float4* op = (float4*)(out + (size_t)p*32);
    #pragma unroll
    for(int t4=0;t4<8;t4++){
        float4 v;
        v.x = fmaf(ct,(float)(4*t4+0),base);
        v.y = fmaf(ct,(float)(4*t4+1),base);
        v.z = fmaf(ct,(float)(4*t4+2),base);
        v.w = fmaf(ct,(float)(4*t4+3),base);
        op[t4]=v;
    }
}

// ---------------- forward DFT over T (32 -> 8 modes) ----------------
__global__ void k_fwdT(const float* __restrict__ x, float2* __restrict__ A){
    __shared__ float2 tw[256];
    for(int i=threadIdx.x;i<256;i+=blockDim.x) tw[i]=g_twTf[i];
    __syncthreads();
    size_t p = (size_t)blockIdx.x*blockDim.x + threadIdx.x;   // pencil (b,c,h,w)
    const float4* xp = (const float4*)(x + p*32);
    float xr[32];
    #pragma unroll
    for(int q=0;q<8;q++){ float4 v=xp[q]; xr[4*q]=v.x; xr[4*q+1]=v.y; xr[4*q+2]=v.z; xr[4*q+3]=v.w; }
    float2 acc[8];
    #pragma unroll
    for(int k=0;k<8;k++) acc[k]=make_float2(0.f,0.f);
    #pragma unroll
    for(int t=0;t<32;t++){
        float xv=xr[t];
        #pragma unroll
        for(int k=0;k<8;k++){
            float2 wv=tw[k*32+t];
            acc[k].x = fmaf(xv,wv.x,acc[k].x);
            acc[k].y = fmaf(xv,wv.y,acc[k].y);
        }
    }
    float4* ap = (float4*)(A + p*8);
    #pragma unroll
    for(int k=0;k<4;k++) ap[k]=make_float4(acc[2*k].x,acc[2*k].y,acc[2*k+1].x,acc[2*k+1].y);
}

// ---------------- forward DFT over W (64 -> 16 modes) ----------------
__global__ void k_fwdW(const float2* __restrict__ A, float2* __restrict__ Bc){
    __shared__ float2 As[512];
    __shared__ float2 tw[1024];
    int bch = blockIdx.x;                               // (b,c,h)
    const float2* Ap = A + (size_t)bch*512;
    for(int i=threadIdx.x;i<512;i+=128) As[i]=Ap[i];
    for(int i=threadIdx.x;i<1024;i+=128) tw[i]=g_twF64[i];
    __syncthreads();
    int kw = threadIdx.x>>3, kt = threadIdx.x&7;
    float2 acc=make_float2(0.f,0.f);
    #pragma unroll 8
    for(int w=0;w<64;w++){
        float2 a=As[w*8+kt], t=tw[kw*64+w];
        acc.x = fmaf(t.x,a.x,fmaf(-t.y,a.y,acc.x));
        acc.y = fmaf(t.x,a.y,fmaf( t.y,a.x,acc.y));
    }
    Bc[(size_t)bch*128 + threadIdx.x]=acc;
}

// ---------------- forward DFT over H (64 -> 16 modes) ----------------
__global__ void k_fwdH(const float2* __restrict__ Bc, float2* __restrict__ xf){
    __shared__ float2 rows[256];
    __shared__ float2 tw[1024];
    int bc=blockIdx.x;                                  // (b,c)
    for(int i=threadIdx.x;i<1024;i+=256) tw[i]=g_twF64[i];
    int m=threadIdx.x&127, kh0=(threadIdx.x>>7)*8;
    float2 acc[8];
    #pragma unroll
    for(int j=0;j<8;j++) acc[j]=make_float2(0.f,0.f);
    const float2* Bp = Bc + (size_t)bc*8192;
    for(int h2=0;h2<32;h2++){
        __syncthreads();
        rows[threadIdx.x]=Bp[h2*256+threadIdx.x];
        __syncthreads();
        #pragma unroll
        for(int s=0;s<2;s++){
            int h=2*h2+s;
            float2 a=rows[s*128+m];
            #pragma unroll
            for(int j=0;j<8;j++){
                float2 t=tw[(kh0+j)*64+h];
                acc[j].x = fmaf(t.x,a.x,fmaf(-t.y,a.y,acc[j].x));
                acc[j].y = fmaf(t.x,a.y,fmaf( t.y,a.x,acc[j].y));
            }
        }
    }
    #pragma unroll
    for(int j=0;j<8;j++) xf[(size_t)bc*2048 + (size_t)(kh0+j)*128 + m]=acc[j];
}

// ---------------- per-mode complex channel mixing ----------------
__global__ void k_mix(const float* __restrict__ wr, const float* __restrict__ wi,
                      const float2* __restrict__ xf, float2* __restrict__ yf){
    __shared__ float2 sw[4*32*32];   // [z'][i][o]
    __shared__ float2 sxf[8*32*4];   // [b][i][z']
    int blk=blockIdx.x;
    int zh=blk&1, y=(blk>>1)&7, x=(blk>>4)&7, q=blk>>7;
    int z0=zh*4;
    int kh=((q&1)<<3)+x, kw=((q&2)<<2)+y;
    int mbase=kh*128+kw*8+z0;
    size_t wbase=(size_t)q*524288 + (size_t)x*64 + (size_t)y*8 + z0;
    for(int idx=threadIdx.x; idx<4096; idx+=256){
        int zz=idx&3, o=(idx>>2)&31, i=idx>>7;
        size_t g=wbase + (size_t)i*16384 + (size_t)o*512 + zz;
        sw[(zz*32+i)*32+o]=make_float2(wr[g], wi[g]);
    }
    for(int idx=threadIdx.x; idx<1024; idx+=256){
        int zz=idx&3, i=(idx>>2)&31, b=idx>>7;
        sxf[(b*32+i)*4+zz]=xf[(size_t)(b*32+i)*2048 + mbase+zz];
    }
    __syncthreads();
    int o=threadIdx.x&31, b=threadIdx.x>>5;
    float2 acc[4];
    #pragma unroll
    for(int zz=0;zz<4;zz++) acc[zz]=make_float2(0.f,0.f);
    for(int i=0;i<32;i++){
        #pragma unroll
        for(int zz=0;zz<4;zz++){
            float2 xv=sxf[(b*32+i)*4+zz];
            float2 wv=sw[(zz*32+i)*32+o];
            acc[zz].x = fmaf(xv.x,wv.x,fmaf(-xv.y,wv.y,acc[zz].x));
            acc[zz].y = fmaf(xv.x,wv.y,fmaf( xv.y,wv.x,acc[zz].y));
        }
    }
    #pragma unroll
    for(int zz=0;zz<4;zz++) yf[(size_t)(b*32+o)*2048 + mbase+zz]=acc[zz];
}

// ---------------- inverse DFT over H (16 modes -> 64) ----------------
__global__ void k_invH(const float2* __restrict__ yf, float2* __restrict__ Y){
    __shared__ float2 syf[2048];
    __shared__ float2 tw[1024];
    int bo=blockIdx.x;                                  // (b,o)
    for(int i=threadIdx.x;i<2048;i+=256) syf[i]=yf[(size_t)bo*2048+i];
    for(int i=threadIdx.x;i<1024;i+=256) tw[i]=g_twI64[i];
    __syncthreads();
    int m=threadIdx.x&127, hg=threadIdx.x>>7;
    for(int j=0;j<32;j++){
        int h=j*2+hg;
        float2 acc=make_float2(0.f,0.f);
        #pragma unroll
        for(int k=0;k<16;k++){
            float2 t=tw[h*16+k], a=syf[k*128+m];
            acc.x = fmaf(t.x,a.x,fmaf(-t.y,a.y,acc.x));
            acc.y = fmaf(t.x,a.y,fmaf( t.y,a.x,acc.y));
        }
        Y[(size_t)bo*8192 + (size_t)h*128 + m]=acc;
    }
}

// ---------------- inverse DFT over W (16 modes -> 64) ----------------
__global__ void k_invW(const float2* __restrict__ Y, float2* __restrict__ Z){
    __shared__ float2 sy[128];
    int boh=blockIdx.x;                                 // (b,o,h)
    if(threadIdx.x<128) sy[threadIdx.x]=Y[(size_t)boh*128+threadIdx.x];
    __syncthreads();
    int w=threadIdx.x&63, kg=threadIdx.x>>6;
    float2 acc[4];
    #pragma unroll
    for(int j=0;j<4;j++) acc[j]=make_float2(0.f,0.f);
    #pragma unroll
    for(int k=0;k<16;k++){
        float2 t=__ldg(&g_twI64[w*16+k]);
        #pragma unroll
        for(int j=0;j<4;j++){
            float2 a=sy[k*8+kg*4+j];
            acc[j].x = fmaf(t.x,a.x,fmaf(-t.y,a.y,acc[j].x));
            acc[j].y = fmaf(t.x,a.y,fmaf( t.y,a.x,acc[j].y));
        }
    }
    float4* zp=(float4*)(Z + (size_t)boh*512 + (size_t)w*8 + kg*4);
    zp[0]=make_float4(acc[0].x,acc[0].y,acc[1].x,acc[1].y);
    zp[1]=make_float4(acc[2].x,acc[2].y,acc[3].x,acc[3].y);
}

// ---------------- fused: inverse-T + pointwise conv + bias + GELU ----------------
__global__ void k_fin(const float2* __restrict__ Z, const float* __restrict__ x,
                      const float* __restrict__ pwW, const float* __restrict__ pwB,
                      float* __restrict__ out){
    __shared__ float2 sZ[4*256];     // per-warp [o][k]
    __shared__ float2 stw[256];      // [k][t]
    __shared__ float  spw[1024];     // [o][i]
    for(int i=threadIdx.x;i<256;i+=128){ int k=i>>5, t=i&31; stw[i]=g_twTi[t*8+k]; }
    for(int i=threadIdx.x;i<1024;i+=128) spw[i]=pwW[i];
    int warp=threadIdx.x>>5, lane=threadIdx.x&31;
    int P=blockIdx.x*4+warp;                 // pencil (b,hw)
    int hw=P&4095, b=P>>12;
    const float2* zp = Z + (size_t)b*1048576 + (size_t)hw*8;
    #pragma unroll
    for(int r=0;r<8;r++){
        int idx=r*32+lane;
        sZ[warp*256+idx]=zp[(size_t)(idx>>3)*32768 + (idx&7)];
    }
    __syncthreads();
    float xr[32];
    #pragma unroll
    for(int i=0;i<32;i++) xr[i]=x[(size_t)b*4194304 + (size_t)i*131072 + (size_t)hw*32 + lane];
    float* op = out + (size_t)b*4194304 + (size_t)hw*32 + lane;
    for(int o=0;o<32;o++){
        float a=__ldg(&pwB[o]);
        #pragma unroll
        for(int i=0;i<32;i++) a=fmaf(spw[o*32+i],xr[i],a);
        #pragma unroll
        for(int k=0;k<8;k++){
            float2 zv=sZ[warp*256+o*8+k];
            float2 t=stw[k*32+lane];
            a = fmaf(t.x,zv.x,fmaf(-t.y,zv.y,a));
        }
        op[(size_t)o*131072] = gelu_f(a);
    }
}

// ---------------- tail: q1 -> GELU -> q2, transposed output ----------------
__global__ void k_tail(const float* __restrict__ x, const float* __restrict__ q1w,
                       const float* __restrict__ q1b, const float* __restrict__ q2w,
                       const float* __restrict__ q2b, float* __restrict__ out){
    __shared__ float sq1[2048];
    __shared__ float sq2[192];
    __shared__ float sout[768];
    for(int i=threadIdx.x;i<2048;i+=256) sq1[i]=q1w[i];
    if(threadIdx.x<192) sq2[threadIdx.x]=q2w[threadIdx.x];
    int warp=threadIdx.x>>5, lane=threadIdx.x&31;
    int P=blockIdx.x*8+warp;
    int hw=P&4095, b=P>>12;
    __syncthreads();
    float xr[32];
    #pragma unroll
    for(int i=0;i<32;i++) xr[i]=x[(size_t)b*4194304 + (size_t)i*131072 + (size_t)hw*32 + lane];
    float a0=__ldg(&q2b[0]), a1=__ldg(&q2b[1]), a2=__ldg(&q2b[2]);
    for(int o2=0;o2<64;o2++){
        float a=__ldg(&q1b[o2]);
        #pragma unroll
        for(int i=0;i<32;i++) a=fmaf(sq1[o2*32+i],xr[i],a);
        a=gelu_f(a);
        a0=fmaf(sq2[o2],a,a0);
        a1=fmaf(sq2[64+o2],a,a1);
        a2=fmaf(sq2[128+o2],a,a2);
    }
    sout[(lane*3+0)*8+warp]=a0;
    sout[(lane*3+1)*8+warp]=a1;
    sout[(lane*3+2)*8+warp]=a2;
    __syncthreads();
    int Pb=blockIdx.x*8;
    int hwb=Pb&4095, bb=Pb>>12;
    for(int idx=threadIdx.x; idx<768; idx+=256){
        int wq=idx&7, co=(idx>>3)%3, t=idx/24;
        out[ ((size_t)(bb*32+t)*3+co)*4096 + hwb + wq ] = sout[idx];
    }
}

// ---------------- launch ----------------
extern "C" void kernel_launch(void* const* d_in, const int* in_sizes, int n_in,
                              void* d_out, int out_size){
    const float* x_t=(const float*)d_in[0];
    const float* p_w=(const float*)d_in[1];
    const float* p_b=(const float*)d_in[2];
    const float* swr=(const float*)d_in[3];
    const float* swi=(const float*)d_in[4];
    const float* pww=(const float*)d_in[5];
    const float* pwb=(const float*)d_in[6];
    const float* q1w=(const float*)d_in[7];
    const float* q1b=(const float*)d_in[8];
    const float* q2w=(const float*)d_in[9];
    const float* q2b=(const float*)d_in[10];
    float* out=(float*)d_out;

    float *b0,*b1; float2 *AZ,*BY,*XF,*YF;
    cudaGetSymbolAddress((void**)&b0, g_buf0);
    cudaGetSymbolAddress((void**)&b1, g_buf1);
    cudaGetSymbolAddress((void**)&AZ, g_AZ);
    cudaGetSymbolAddress((void**)&BY, g_BY);
    cudaGetSymbolAddress((void**)&XF, g_xf);
    cudaGetSymbolAddress((void**)&YF, g_yf);

    k_init_tw<<<1,256>>>();
    k_head<<<4096,256>>>(x_t,p_w,p_b,b0);

    float* cur=b0; float* nxt=b1;
    for(int l=0;l<4;l++){
        k_fwdT<<<4096,256>>>(cur,AZ);
        k_fwdW<<<16384,128>>>(AZ,BY);
        k_fwdH<<<256,256>>>(BY,XF);
        k_mix<<<512,256>>>(swr+(size_t)l*2097152, swi+(size_t)l*2097152, XF, YF);
        k_invH<<<256,256>>>(YF,BY);
        k_invW<<<16384,128>>>(BY,AZ);
        k_fin<<<8192,128>>>(AZ,cur,pww+(size_t)l*1024,pwb+(size_t)l*32,nxt);
        float* tmp=cur; cur=nxt; nxt=tmp;
    }
    k_tail<<<4096,256>>>(cur,q1w,q1b,q2w,q2b,out);
}

// round 2
// speedup vs baseline: 1.2201x; 1.2201x over previous
#include <cuda_runtime.h>
#include <math.h>

// Problem constants
#define BB 8
#define CW 32
#define HH 64
#define WW 64
#define TT 32
#define NM 2048

// ---------------- scratch (device globals; no allocation) ----------------
__device__ float  g_buf0[BB*CW*HH*WW*TT];          // 134MB
__device__ float  g_buf1[BB*CW*HH*WW*TT];          // 134MB
__device__ float2 g_Z[BB*CW*HH*8*WW];              // 67MB  Z[b][o][h][kt][w]
__device__ float2 g_BY[BB*CW*HH*16*8];             // 16.8MB Bc[b,c][h][kw*8+kt]
__device__ float2 g_xf[BB*CW*NM];                  // 4.2MB
__device__ float2 g_yf[BB*CW*NM];                  // 4.2MB
__device__ float2 g_twTf[8*32];                    // [kt][t]  e^{-2pi i k t/32}
__device__ float2 g_twF64[64*16];                  // [n][ki]  e^{-2pi i f(ki) n/64}
__device__ float2 g_twI64[64*16];                  // [n][ki]  e^{+2pi i f(ki) n/64}
__device__ float2 g_twTi[32*8];                    // [t][k]   scaled inverse-T

__device__ __forceinline__ float gelu_f(float v){
    return 0.5f*v*(1.0f + erff(v*0.7071067811865476f));
}

// ---------------- twiddle init ----------------
__global__ void k_init_tw(){
    const double PI = 3.14159265358979323846;
    int tid = threadIdx.x;
    for(int idx=tid; idx<8*32; idx+=256){
        int k=idx/32, t=idx%32;
        double a = -2.0*PI*(double)(k*t)/32.0;
        g_twTf[idx] = make_float2((float)cos(a),(float)sin(a));
    }
    for(int idx=tid; idx<64*16; idx+=256){
        int n=idx>>4, ki=idx&15;
        int f = ki<8 ? ki : ki+48;
        double a = -2.0*PI*(double)(f*n)/64.0;
        g_twF64[idx] = make_float2((float)cos(a),(float)sin(a));
        double ai = 2.0*PI*(double)(f*n)/64.0;
        g_twI64[idx] = make_float2((float)cos(ai),(float)sin(ai));
    }
    for(int idx=tid; idx<32*8; idx+=256){
        int t=idx/8, k=idx%8;
        double sc = (k==0 ? 1.0 : 2.0)/131072.0;
        double a = 2.0*PI*(double)(k*t)/32.0;
        g_twTi[idx] = make_float2((float)(sc*cos(a)),(float)(sc*sin(a)));
    }
}

// ---------------- head: lift ----------------
__global__ void k_head(const float* __restrict__ xt, const float* __restrict__ pw,
                       const float* __restrict__ pb, float* __restrict__ out){
    int p = blockIdx.x*blockDim.x + threadIdx.x;
    int w = p & 63, h = (p>>6)&63, c = (p>>12)&31, b = p>>17;
    float base = pb[c];
    #pragma unroll
    for(int j=0;j<3;j++) base = fmaf(pw[c*6+j], xt[((b*3+j)*64+h)*64+w], base);
    base = fmaf(pw[c*6+3], (float)h*(1.0f/63.0f), base);
    base = fmaf(pw[c*6+4], (float)w*(1.0f/63.0f), base);
    float ct = pw[c*6+5]*(1.0f/31.0f);
    float4* op = (float4*)(out + (size_t)p*32);
    #pragma unroll
    for(int t4=0;t4<8;t4++){
        float4 v;
        v.x = fmaf(ct,(float)(4*t4+0),base);
        v.y = fmaf(ct,(float)(4*t4+1),base);
        v.z = fmaf(ct,(float)(4*t4+2),base);
        v.w = fmaf(ct,(float)(4*t4+3),base);
        op[t4]=v;
    }
}

// ---------------- fused forward DFT over T then W ----------------
// block = (b,c,h) row; 128 threads
__global__ void k_fwd2(const float* __restrict__ x, float2* __restrict__ Bc){
    __shared__ float2 As[8*66];      // [kt][w] padded row stride 66
    __shared__ float2 twT[256];      // [kt][t]
    __shared__ float2 twW[1024];     // [w][kw]
    int tid = threadIdx.x;
    for(int i=tid;i<256;i+=128) twT[i]=g_twTf[i];
    for(int i=tid;i<1024;i+=128) twW[i]=g_twF64[i];
    int bch = blockIdx.x;
    int w = tid&63, ktq = tid>>6;
    // step1: T-DFT (32 -> 8 modes), this thread: 4 kt for its w
    const float4* xp = (const float4*)(x + (size_t)bch*2048 + (size_t)w*32);
    float xr[32];
    #pragma unroll
    for(int q=0;q<8;q++){ float4 v=xp[q]; xr[4*q]=v.x; xr[4*q+1]=v.y; xr[4*q+2]=v.z; xr[4*q+3]=v.w; }
    __syncthreads();
    float2 acc[4];
    #pragma unroll
    for(int j=0;j<4;j++) acc[j]=make_float2(0.f,0.f);
    #pragma unroll
    for(int t=0;t<32;t++){
        float xv=xr[t];
        #pragma unroll
        for(int j=0;j<4;j++){
            float2 tw=twT[(ktq*4+j)*32+t];
            acc[j].x = fmaf(xv,tw.x,acc[j].x);
            acc[j].y = fmaf(xv,tw.y,acc[j].y);
        }
    }
    #pragma unroll
    for(int j=0;j<4;j++) As[(ktq*4+j)*66 + w] = acc[j];
    __syncthreads();
    // step2: W-DFT (64 -> 16 modes); thread = (kw, kt)
    int kw = tid>>3, kt = tid&7;
    float2 s=make_float2(0.f,0.f);
    #pragma unroll 8
    for(int ww=0;ww<64;ww++){
        float2 a=As[kt*66+ww], t=twW[ww*16+kw];
        s.x = fmaf(t.x,a.x,fmaf(-t.y,a.y,s.x));
        s.y = fmaf(t.x,a.y,fmaf( t.y,a.x,s.y));
    }
    Bc[(size_t)bch*128 + tid]=s;     // m = kw*8+kt
}

// ---------------- forward DFT over H (64 -> 16 modes) ----------------
__global__ void k_fwdH(const float2* __restrict__ Bc, float2* __restrict__ xf){
    __shared__ float2 rows[256];
    __shared__ float2 tw[1024];      // [h][kh]
    int bc=blockIdx.x;
    for(int i=threadIdx.x;i<1024;i+=256) tw[i]=g_twF64[i];
    int m=threadIdx.x&127, kh0=(threadIdx.x>>7)*8;
    float2 acc[8];
    #pragma unroll
    for(int j=0;j<8;j++) acc[j]=make_float2(0.f,0.f);
    const float2* Bp = Bc + (size_t)bc*8192;
    for(int h2=0;h2<32;h2++){
        __syncthreads();
        rows[threadIdx.x]=Bp[h2*256+threadIdx.x];
        __syncthreads();
        #pragma unroll
        for(int s=0;s<2;s++){
            int h=2*h2+s;
            float2 a=rows[s*128+m];
            #pragma unroll
            for(int j=0;j<8;j++){
                float2 t=tw[h*16+kh0+j];
                acc[j].x = fmaf(t.x,a.x,fmaf(-t.y,a.y,acc[j].x));
                acc[j].y = fmaf(t.x,a.y,fmaf( t.y,a.x,acc[j].y));
            }
        }
    }
    #pragma unroll
    for(int j=0;j<8;j++) xf[(size_t)bc*2048 + (size_t)(kh0+j)*128 + m]=acc[j];
}

// ---------------- per-mode complex channel mixing ----------------
__global__ void k_mix(const float* __restrict__ wr, const float* __restrict__ wi,
                      const float2* __restrict__ xf, float2* __restrict__ yf){
    __shared__ float2 sw[4*32*32];
    __shared__ float2 sxf[8*32*4];
    int blk=blockIdx.x;
    int zh=blk&1, y=(blk>>1)&7, x=(blk>>4)&7, q=blk>>7;
    int z0=zh*4;
    int kh=((q&1)<<3)+x, kw=((q&2)<<2)+y;
    int mbase=kh*128+kw*8+z0;
    size_t wbase=(size_t)q*524288 + (size_t)x*64 + (size_t)y*8 + z0;
    for(int idx=threadIdx.x; idx<4096; idx+=256){
        int zz=idx&3, o=(idx>>2)&31, i=idx>>7;
        size_t g=wbase + (size_t)i*16384 + (size_t)o*512 + zz;
        sw[(zz*32+i)*32+o]=make_float2(wr[g], wi[g]);
    }
    for(int idx=threadIdx.x; idx<1024; idx+=256){
        int zz=idx&3, i=(idx>>2)&31, b=idx>>7;
        sxf[(b*32+i)*4+zz]=xf[(size_t)(b*32+i)*2048 + mbase+zz];
    }
    __syncthreads();
    int o=threadIdx.x&31, b=threadIdx.x>>5;
    float2 acc[4];
    #pragma unroll
    for(int zz=0;zz<4;zz++) acc[zz]=make_float2(0.f,0.f);
    for(int i=0;i<32;i++){
        #pragma unroll
        for(int zz=0;zz<4;zz++){
            float2 xv=sxf[(b*32+i)*4+zz];
            float2 wv=sw[(zz*32+i)*32+o];
            acc[zz].x = fmaf(xv.x,wv.x,fmaf(-xv.y,wv.y,acc[zz].x));
            acc[zz].y = fmaf(xv.x,wv.y,fmaf( xv.y,wv.x,acc[zz].y));
        }
    }
    #pragma unroll
    for(int zz=0;zz<4;zz++) yf[(size_t)(b*32+o)*2048 + mbase+zz]=acc[zz];
}

// ---------------- fused inverse DFT over H then W ----------------
// block = (b,o); 256 threads; output Z[b][o][h][kt][w]
__global__ void k_inv2(const float2* __restrict__ yf, float2* __restrict__ Z){
    __shared__ float2 twI[1024];     // [h][kh]
    __shared__ float2 Ysh[256];      // 2 h rows x [kw*8+kt]
    int tid=threadIdx.x;
    int bo=blockIdx.x;
    for(int i=tid;i<1024;i+=256) twI[i]=g_twI64[i];
    // step1 state: thread (m, hg) holds all 16 kh coefficients for its m
    int m=tid&127, hg=tid>>7;
    float2 a[16];
    #pragma unroll
    for(int kh=0;kh<16;kh++) a[kh]=yf[(size_t)bo*2048 + kh*128 + m];
    // step2 state: thread (w, g) holds its 16 inverse-W twiddles
    int w=tid&63, g=tid>>6;
    float2 tww[16];
    #pragma unroll
    for(int kw=0;kw<16;kw++) tww[kw]=g_twI64[w*16+kw];
    __syncthreads();
    float2* zb = Z + (size_t)bo*32768;
    for(int r=0;r<32;r++){
        // invH for h = 2r+hg
        int h=2*r+hg;
        float2 acc=make_float2(0.f,0.f);
        #pragma unroll
        for(int kh=0;kh<16;kh++){
            float2 t=twI[h*16+kh];
            acc.x = fmaf(t.x,a[kh].x,fmaf(-t.y,a[kh].y,acc.x));
            acc.y = fmaf(t.x,a[kh].y,fmaf( t.y,a[kh].x,acc.y));
        }
        Ysh[hg*128+m]=acc;
        __syncthreads();
        // invW for the 2 h rows; thread (w,g): kt = g*2 + {0,1}
        #pragma unroll
        for(int hh=0;hh<2;hh++){
            int hx=2*r+hh;
            #pragma unroll
            for(int kt2=0;kt2<2;kt2++){
                int kt=g*2+kt2;
                float2 s=make_float2(0.f,0.f);
                #pragma unroll
                for(int kw=0;kw<16;kw++){
                    float2 av=Ysh[hh*128+kw*8+kt];
                    s.x = fmaf(tww[kw].x,av.x,fmaf(-tww[kw].y,av.y,s.x));
                    s.y = fmaf(tww[kw].x,av.y,fmaf( tww[kw].y,av.x,s.y));
                }
                zb[(size_t)hx*512 + kt*64 + w]=s;
            }
        }
        __syncthreads();
    }
}

// ---------------- fused: inverse-T + pointwise conv + bias + GELU ----------------
// block = 8 pencils (same b,h; w0..w0+7); 256 threads
__global__ void k_fin(const float2* __restrict__ Z, const float* __restrict__ x,
                      const float* __restrict__ pwW, const float* __restrict__ pwB,
                      float* __restrict__ out){
    __shared__ float2 sZ[2048];      // [o][kt][wi]
    __shared__ float2 stw[256];      // [k][t]
    __shared__ float  spw[1024];
    int tid=threadIdx.x;
    { int k=tid>>5, t=tid&31; stw[tid]=g_twTi[t*8+k]; }
    for(int i=tid;i<1024;i+=256) spw[i]=pwW[i];
    int warp=tid>>5, lane=tid&31;
    int Pb=blockIdx.x*8;
    int hw0=Pb&4095, b=Pb>>12;
    int h=hw0>>6, w0=hw0&63;
    const float2* zbase = Z + (size_t)b*1048576 + (size_t)h*512 + w0;
    for(int i=tid;i<2048;i+=256)
        sZ[i]=zbase[(size_t)(i>>6)*32768 + (size_t)((i>>3)&7)*64 + (i&7)];
    __syncthreads();
    int hw=hw0+warp, wi=warp;
    float xr[32];
    #pragma unroll
    for(int i=0;i<32;i++) xr[i]=x[(size_t)b*4194304 + (size_t)i*131072 + (size_t)hw*32 + lane];
    float* op = out + (size_t)b*4194304 + (size_t)hw*32 + lane;
    for(int o=0;o<32;o++){
        float aa=__ldg(&pwB[o]);
        #pragma unroll
        for(int i=0;i<32;i++) aa=fmaf(spw[o*32+i],xr[i],aa);
        #pragma unroll
        for(int k=0;k<8;k++){
            float2 zv=sZ[o*64+k*8+wi];
            float2 t=stw[k*32+lane];
            aa = fmaf(t.x,zv.x,fmaf(-t.y,zv.y,aa));
        }
        op[(size_t)o*131072] = gelu_f(aa);
    }
}

// ---------------- tail: q1 -> GELU -> q2, transposed output ----------------
__global__ void k_tail(const float* __restrict__ x, const float* __restrict__ q1w,
                       const float* __restrict__ q1b, const float* __restrict__ q2w,
                       const float* __restrict__ q2b, float* __restrict__ out){
    __shared__ float sq1[2048];
    __shared__ float sq2[192];
    __shared__ float sout[768];
    for(int i=threadIdx.x;i<2048;i+=256) sq1[i]=q1w[i];
    if(threadIdx.x<192) sq2[threadIdx.x]=q2w[threadIdx.x];
    int warp=threadIdx.x>>5, lane=threadIdx.x&31;
    int P=blockIdx.x*8+warp;
    int hw=P&4095, b=P>>12;
    __syncthreads();
    float xr[32];
    #pragma unroll
    for(int i=0;i<32;i++) xr[i]=x[(size_t)b*4194304 + (size_t)i*131072 + (size_t)hw*32 + lane];
    float a0=__ldg(&q2b[0]), a1=__ldg(&q2b[1]), a2=__ldg(&q2b[2]);
    for(int o2=0;o2<64;o2++){
        float a=__ldg(&q1b[o2]);
        #pragma unroll
        for(int i=0;i<32;i++) a=fmaf(sq1[o2*32+i],xr[i],a);
        a=gelu_f(a);
        a0=fmaf(sq2[o2],a,a0);
        a1=fmaf(sq2[64+o2],a,a1);
        a2=fmaf(sq2[128+o2],a,a2);
    }
    sout[(lane*3+0)*8+warp]=a0;
    sout[(lane*3+1)*8+warp]=a1;
    sout[(lane*3+2)*8+warp]=a2;
    __syncthreads();
    int Pb=blockIdx.x*8;
    int hwb=Pb&4095, bb=Pb>>12;
    for(int idx=threadIdx.x; idx<768; idx+=256){
        int wq=idx&7, co=(idx>>3)%3, t=idx/24;
        out[ ((size_t)(bb*32+t)*3+co)*4096 + hwb + wq ] = sout[idx];
    }
}

// ---------------- launch ----------------
extern "C" void kernel_launch(void* const* d_in, const int* in_sizes, int n_in,
                              void* d_out, int out_size){
    const float* x_t=(const float*)d_in[0];
    const float* p_w=(const float*)d_in[1];
    const float* p_b=(const float*)d_in[2];
    const float* swr=(const float*)d_in[3];
    const float* swi=(const float*)d_in[4];
    const float* pww=(const float*)d_in[5];
    const float* pwb=(const float*)d_in[6];
    const float* q1w=(const float*)d_in[7];
    const float* q1b=(const float*)d_in[8];
    const float* q2w=(const float*)d_in[9];
    const float* q2b=(const float*)d_in[10];
    float* out=(float*)d_out;

    float *b0,*b1; float2 *Z,*BY,*XF,*YF;
    cudaGetSymbolAddress((void**)&b0, g_buf0);
    cudaGetSymbolAddress((void**)&b1, g_buf1);
    cudaGetSymbolAddress((void**)&Z,  g_Z);
    cudaGetSymbolAddress((void**)&BY, g_BY);
    cudaGetSymbolAddress((void**)&XF, g_xf);
    cudaGetSymbolAddress((void**)&YF, g_yf);

    k_init_tw<<<1,256>>>();
    k_head<<<4096,256>>>(x_t,p_w,p_b,b0);

    float* cur=b0; float* nxt=b1;
    for(int l=0;l<4;l++){
        k_fwd2<<<16384,128>>>(cur,BY);
        k_fwdH<<<256,256>>>(BY,XF);
        k_mix<<<512,256>>>(swr+(size_t)l*2097152, swi+(size_t)l*2097152, XF, YF);
        k_inv2<<<256,256>>>(YF,Z);
        k_fin<<<4096,256>>>(Z,cur,pww+(size_t)l*1024,pwb+(size_t)l*32,nxt);
        float* tmp=cur; cur=nxt; nxt=tmp;
    }
    k_tail<<<4096,256>>>(cur,q1w,q1b,q2w,q2b,out);
}

// round 3
// speedup vs baseline: 1.2883x; 1.0559x over previous
#include <cuda_runtime.h>
#include <math.h>

#define BB 8
#define CW 32
#define HH 64
#define WW 64
#define TT 32
#define NM 2048

// ---------------- scratch ----------------
__device__ float  g_buf0[BB*CW*HH*WW*TT];          // 134MB
__device__ float  g_buf1[BB*CW*HH*WW*TT];          // 134MB
__device__ float2 g_Z[BB*CW*HH*8*WW];              // 67MB  Z[b][o][h][kt][w]
__device__ float2 g_BY[BB*CW*HH*16*8];             // 16.8MB
__device__ float2 g_xf[BB*CW*NM];                  // 4.2MB
__device__ float2 g_yf[BB*CW*NM];                  // 4.2MB
__device__ float2 g_twTf2[32*8];                   // [t][kt]  e^{-2pi i k t/32}
__device__ float2 g_twF64[64*16];                  // [n][ki]  e^{-2pi i f(ki) n/64}
__device__ float2 g_twI64[64*16];                  // [n][ki]  e^{+2pi i f(ki) n/64}
__device__ float2 g_twTi[32*8];                    // [t][k]   scaled inverse-T

__device__ __forceinline__ float gelu_f(float v){
    return 0.5f*v*(1.0f + erff(v*0.7071067811865476f));
}

// ---------------- twiddle init ----------------
__global__ void k_init_tw(){
    const double PI = 3.14159265358979323846;
    int tid = threadIdx.x;
    for(int idx=tid; idx<32*8; idx+=256){
        int t=idx>>3, k=idx&7;
        double a = -2.0*PI*(double)(k*t)/32.0;
        g_twTf2[idx] = make_float2((float)cos(a),(float)sin(a));
    }
    for(int idx=tid; idx<64*16; idx+=256){
        int n=idx>>4, ki=idx&15;
        int f = ki<8 ? ki : ki+48;
        double a = -2.0*PI*(double)(f*n)/64.0;
        g_twF64[idx] = make_float2((float)cos(a),(float)sin(a));
        double ai = 2.0*PI*(double)(f*n)/64.0;
        g_twI64[idx] = make_float2((float)cos(ai),(float)sin(ai));
    }
    for(int idx=tid; idx<32*8; idx+=256){
        int t=idx/8, k=idx%8;
        double sc = (k==0 ? 1.0 : 2.0)/131072.0;
        double a = 2.0*PI*(double)(k*t)/32.0;
        g_twTi[idx] = make_float2((float)(sc*cos(a)),(float)(sc*sin(a)));
    }
}

// ---------------- head ----------------
__global__ void k_head(const float* __restrict__ xt, const float* __restrict__ pw,
                       const float* __restrict__ pb, float* __restrict__ out){
    int p = blockIdx.x*blockDim.x + threadIdx.x;
    int w = p & 63, h = (p>>6)&63, c = (p>>12)&31, b = p>>17;
    float base = pb[c];
    #pragma unroll
    for(int j=0;j<3;j++) base = fmaf(pw[c*6+j], xt[((b*3+j)*64+h)*64+w], base);
    base = fmaf(pw[c*6+3], (float)h*(1.0f/63.0f), base);
    base = fmaf(pw[c*6+4], (float)w*(1.0f/63.0f), base);
    float ct = pw[c*6+5]*(1.0f/31.0f);
    float4* op = (float4*)(out + (size_t)p*32);
    #pragma unroll
    for(int t4=0;t4<8;t4++){
        float4 v;
        v.x = fmaf(ct,(float)(4*t4+0),base);
        v.y = fmaf(ct,(float)(4*t4+1),base);
        v.z = fmaf(ct,(float)(4*t4+2),base);
        v.w = fmaf(ct,(float)(4*t4+3),base);
        op[t4]=v;
    }
}

// ---------------- fused forward DFT over T then W ----------------
__global__ void k_fwd2(const float* __restrict__ x, float2* __restrict__ Bc){
    __shared__ float2 As[8*66];
    __shared__ float2 twT[256];      // [t][kt]
    __shared__ float2 twW[1024];     // [w][kw]
    int tid = threadIdx.x;
    for(int i=tid;i<256;i+=128) twT[i]=g_twTf2[i];
    for(int i=tid;i<1024;i+=128) twW[i]=g_twF64[i];
    int bch = blockIdx.x;
    int w = tid&63, ktq = tid>>6;
    const float4* xp = (const float4*)(x + (size_t)bch*2048 + (size_t)w*32);
    float xr[32];
    #pragma unroll
    for(int q=0;q<8;q++){ float4 v=xp[q]; xr[4*q]=v.x; xr[4*q+1]=v.y; xr[4*q+2]=v.z; xr[4*q+3]=v.w; }
    __syncthreads();
    float2 acc[4];
    #pragma unroll
    for(int j=0;j<4;j++) acc[j]=make_float2(0.f,0.f);
    #pragma unroll
    for(int t=0;t<32;t++){
        float xv=xr[t];
        float4 q0 = *(const float4*)&twT[t*8+ktq*4];
        float4 q1 = *(const float4*)&twT[t*8+ktq*4+2];
        acc[0].x=fmaf(xv,q0.x,acc[0].x); acc[0].y=fmaf(xv,q0.y,acc[0].y);
        acc[1].x=fmaf(xv,q0.z,acc[1].x); acc[1].y=fmaf(xv,q0.w,acc[1].y);
        acc[2].x=fmaf(xv,q1.x,acc[2].x); acc[2].y=fmaf(xv,q1.y,acc[2].y);
        acc[3].x=fmaf(xv,q1.z,acc[3].x); acc[3].y=fmaf(xv,q1.w,acc[3].y);
    }
    #pragma unroll
    for(int j=0;j<4;j++) As[(ktq*4+j)*66 + w] = acc[j];
    __syncthreads();
    int kw = tid>>3, kt = tid&7;
    float2 s=make_float2(0.f,0.f);
    #pragma unroll 8
    for(int ww=0;ww<64;ww++){
        float2 a=As[kt*66+ww], t=twW[ww*16+kw];
        s.x = fmaf(t.x,a.x,fmaf(-t.y,a.y,s.x));
        s.y = fmaf(t.x,a.y,fmaf( t.y,a.x,s.y));
    }
    Bc[(size_t)bch*128 + tid]=s;
}

// ---------------- forward DFT over H (64 -> 16 modes) ----------------
// grid = (b,c)*2 halves ; 512 threads; thread = (m, khq) with 2 kh each
__global__ void k_fwdH(const float2* __restrict__ Bc, float2* __restrict__ xf){
    __shared__ float2 tw[1024];      // [h][kh]
    int tid=threadIdx.x;
    int blk=blockIdx.x; int bc=blk>>1, half=blk&1;
    for(int i=tid;i<1024;i+=512) tw[i]=g_twF64[i];
    __syncthreads();
    int m=tid&127, khq=tid>>7;
    int kh0 = half*8 + khq*2;
    const float2* Bp = Bc + (size_t)bc*8192 + m;
    float2 a0=make_float2(0.f,0.f), a1=make_float2(0.f,0.f);
    #pragma unroll 4
    for(int h=0;h<64;h++){
        float2 v = Bp[(size_t)h*128];
        float4 tq = *(const float4*)&tw[h*16+kh0];
        a0.x = fmaf(tq.x,v.x,fmaf(-tq.y,v.y,a0.x));
        a0.y = fmaf(tq.x,v.y,fmaf( tq.y,v.x,a0.y));
        a1.x = fmaf(tq.z,v.x,fmaf(-tq.w,v.y,a1.x));
        a1.y = fmaf(tq.z,v.y,fmaf( tq.w,v.x,a1.y));
    }
    xf[(size_t)bc*2048 + (size_t)kh0*128 + m]=a0;
    xf[(size_t)bc*2048 + (size_t)(kh0+1)*128 + m]=a1;
}

// ---------------- per-mode complex channel mixing ----------------
__global__ void k_mix(const float* __restrict__ wr, const float* __restrict__ wi,
                      const float2* __restrict__ xf, float2* __restrict__ yf){
    __shared__ float2 sw[4*32*32];   // [zz][i][o]
    __shared__ float2 sxf[8*32*4];   // [b][i][zz]
    int blk=blockIdx.x;
    int zh=blk&1, y=(blk>>1)&7, x=(blk>>4)&7, q=blk>>7;
    int z0=zh*4;
    int kh=((q&1)<<3)+x, kw=((q&2)<<2)+y;
    int mbase=kh*128+kw*8+z0;
    size_t wbase=(size_t)q*524288 + (size_t)x*64 + (size_t)y*8 + z0;
    const float4* wr4=(const float4*)wr;
    const float4* wi4=(const float4*)wi;
    for(int idx=threadIdx.x; idx<1024; idx+=256){
        int o=idx&31, i=idx>>5;
        size_t g4=(wbase>>2) + (size_t)i*4096 + (size_t)o*128;
        float4 r=wr4[g4], im=wi4[g4];
        sw[(0*32+i)*32+o]=make_float2(r.x,im.x);
        sw[(1*32+i)*32+o]=make_float2(r.y,im.y);
        sw[(2*32+i)*32+o]=make_float2(r.z,im.z);
        sw[(3*32+i)*32+o]=make_float2(r.w,im.w);
    }
    const float4* xf4=(const float4*)xf;
    for(int idx=threadIdx.x; idx<512; idx+=256){
        int zh2=idx&1, i=(idx>>1)&31, b=idx>>6;
        float4 v = xf4[(((size_t)(b*32+i)*2048+mbase)>>1) + zh2];
        sxf[(b*32+i)*4+zh2*2]   = make_float2(v.x,v.y);
        sxf[(b*32+i)*4+zh2*2+1] = make_float2(v.z,v.w);
    }
    __syncthreads();
    int o=threadIdx.x&31, b=threadIdx.x>>5;
    float2 acc[4];
    #pragma unroll
    for(int zz=0;zz<4;zz++) acc[zz]=make_float2(0.f,0.f);
    for(int i=0;i<32;i++){
        float4 xq0 = *(const float4*)&sxf[(b*32+i)*4];
        float4 xq1 = *(const float4*)&sxf[(b*32+i)*4+2];
        float2 w0=sw[(0*32+i)*32+o], w1=sw[(1*32+i)*32+o];
        float2 w2=sw[(2*32+i)*32+o], w3=sw[(3*32+i)*32+o];
        acc[0].x = fmaf(xq0.x,w0.x,fmaf(-xq0.y,w0.y,acc[0].x));
        acc[0].y = fmaf(xq0.x,w0.y,fmaf( xq0.y,w0.x,acc[0].y));
        acc[1].x = fmaf(xq0.z,w1.x,fmaf(-xq0.w,w1.y,acc[1].x));
        acc[1].y = fmaf(xq0.z,w1.y,fmaf( xq0.w,w1.x,acc[1].y));
        acc[2].x = fmaf(xq1.x,w2.x,fmaf(-xq1.y,w2.y,acc[2].x));
        acc[2].y = fmaf(xq1.x,w2.y,fmaf( xq1.y,w2.x,acc[2].y));
        acc[3].x = fmaf(xq1.z,w3.x,fmaf(-xq1.w,w3.y,acc[3].x));
        acc[3].y = fmaf(xq1.z,w3.y,fmaf( xq1.w,w3.x,acc[3].y));
    }
    float4* yp = (float4*)&yf[(size_t)(b*32+o)*2048 + mbase];
    yp[0]=make_float4(acc[0].x,acc[0].y,acc[1].x,acc[1].y);
    yp[1]=make_float4(acc[2].x,acc[2].y,acc[3].x,acc[3].y);
}

// ---------------- fused inverse DFT over H then W ----------------
// grid = (b,o)*8 h-groups; 256 threads
__global__ void k_inv2(const float2* __restrict__ yf, float2* __restrict__ Z){
    __shared__ float2 syf[2048];     // [kh][m]
    __shared__ float2 Ysh[1024];     // [hh][m]
    __shared__ float2 twIs[128];     // [hh][kh]
    int tid=threadIdx.x;
    int blk=blockIdx.x; int bo=blk>>3, hq=blk&7; int h0=hq*8;
    for(int i=tid;i<2048;i+=256) syf[i]=yf[(size_t)bo*2048+i];
    if(tid<128) twIs[tid]=g_twI64[h0*16+tid];
    int w=tid&63, g=tid>>6;
    float2 tww[16];
    {
        const float4* twp=(const float4*)(g_twI64 + w*16);
        #pragma unroll
        for(int j=0;j<8;j++){
            float4 v=twp[j];
            tww[2*j]  =make_float2(v.x,v.y);
            tww[2*j+1]=make_float2(v.z,v.w);
        }
    }
    __syncthreads();
    int m=tid&127, hg=tid>>7;
    #pragma unroll
    for(int j=0;j<4;j++){
        int hh=hg*4+j;
        float2 acc=make_float2(0.f,0.f);
        #pragma unroll
        for(int k2=0;k2<8;k2++){
            float4 tq=*(const float4*)&twIs[hh*16+k2*2];
            float2 a0=syf[(k2*2)*128+m], a1=syf[(k2*2+1)*128+m];
            acc.x = fmaf(tq.x,a0.x,fmaf(-tq.y,a0.y,acc.x));
            acc.y = fmaf(tq.x,a0.y,fmaf( tq.y,a0.x,acc.y));
            acc.x = fmaf(tq.z,a1.x,fmaf(-tq.w,a1.y,acc.x));
            acc.y = fmaf(tq.z,a1.y,fmaf( tq.w,a1.x,acc.y));
        }
        Ysh[hh*128+m]=acc;
    }
    __syncthreads();
    float2* zb = Z + (size_t)bo*32768 + (size_t)h0*512;
    #pragma unroll
    for(int hh=0;hh<8;hh++){
        #pragma unroll
        for(int kt2=0;kt2<2;kt2++){
            int kt=g*2+kt2;
            float2 s=make_float2(0.f,0.f);
            #pragma unroll
            for(int kw=0;kw<16;kw++){
                float2 av=Ysh[hh*128+kw*8+kt];
                s.x = fmaf(tww[kw].x,av.x,fmaf(-tww[kw].y,av.y,s.x));
                s.y = fmaf(tww[kw].x,av.y,fmaf( tww[kw].y,av.x,s.y));
            }
            zb[(size_t)hh*512 + kt*64 + w]=s;
        }
    }
}

// ---------------- fused: inverse-T + pointwise conv + bias + GELU ----------------
// block = 8 pencils (same b,h; w0..w0+7); 256 threads
__global__ void k_fin(const float2* __restrict__ Z, const float* __restrict__ x,
                      const float* __restrict__ pwW, const float* __restrict__ pwB,
                      float* __restrict__ out){
    __shared__ float2 sZ[2048];      // [o][wi][kt]
    __shared__ float  spw[1024];
    int tid=threadIdx.x;
    for(int i=tid;i<1024;i+=256) spw[i]=pwW[i];
    int warp=tid>>5, lane=tid&31;
    // per-thread inverse-T twiddles (t = lane)
    float2 twr[8];
    {
        const float4* tp=(const float4*)(g_twTi + lane*8);
        #pragma unroll
        for(int j=0;j<4;j++){
            float4 v=tp[j];
            twr[2*j]  =make_float2(v.x,v.y);
            twr[2*j+1]=make_float2(v.z,v.w);
        }
    }
    int Pb=blockIdx.x*8;
    int hw0=Pb&4095, b=Pb>>12;
    int h=hw0>>6, w0=hw0&63;
    const float2* zbase = Z + (size_t)b*1048576 + (size_t)h*512 + w0;
    for(int i=tid;i<2048;i+=256){
        int o=i>>6, kt=(i>>3)&7, wi=i&7;
        sZ[o*64 + wi*8 + kt]=zbase[(size_t)o*32768 + (size_t)kt*64 + wi];
    }
    __syncthreads();
    int hw=hw0+warp, wi=warp;
    float xr[32];
    #pragma unroll
    for(int i=0;i<32;i++) xr[i]=x[(size_t)b*4194304 + (size_t)i*131072 + (size_t)hw*32 + lane];
    float* op = out + (size_t)b*4194304 + (size_t)hw*32 + lane;
    const float4* spw4=(const float4*)spw;
    for(int o=0;o<32;o++){
        float aa=__ldg(&pwB[o]);
        #pragma unroll
        for(int j=0;j<8;j++){
            float4 wv=spw4[o*8+j];
            aa=fmaf(wv.x,xr[4*j],aa);
            aa=fmaf(wv.y,xr[4*j+1],aa);
            aa=fmaf(wv.z,xr[4*j+2],aa);
            aa=fmaf(wv.w,xr[4*j+3],aa);
        }
        const float4* z4=(const float4*)(sZ + o*64 + wi*8);
        #pragma unroll
        for(int j=0;j<4;j++){
            float4 zz=z4[j];
            aa = fmaf(twr[2*j].x,  zz.x, fmaf(-twr[2*j].y,  zz.y, aa));
            aa = fmaf(twr[2*j+1].x,zz.z, fmaf(-twr[2*j+1].y,zz.w, aa));
        }
        op[(size_t)o*131072] = gelu_f(aa);
    }
}

// ---------------- tail ----------------
__global__ void k_tail(const float* __restrict__ x, const float* __restrict__ q1w,
                       const float* __restrict__ q1b, const float* __restrict__ q2w,
                       const float* __restrict__ q2b, float* __restrict__ out){
    __shared__ float sq1[2048];
    __shared__ float sq2[192];
    __shared__ float sout[768];
    for(int i=threadIdx.x;i<2048;i+=256) sq1[i]=q1w[i];
    if(threadIdx.x<192) sq2[threadIdx.x]=q2w[threadIdx.x];
    int warp=threadIdx.x>>5, lane=threadIdx.x&31;
    int P=blockIdx.x*8+warp;
    int hw=P&4095, b=P>>12;
    __syncthreads();
    float xr[32];
    #pragma unroll
    for(int i=0;i<32;i++) xr[i]=x[(size_t)b*4194304 + (size_t)i*131072 + (size_t)hw*32 + lane];
    float a0=__ldg(&q2b[0]), a1=__ldg(&q2b[1]), a2=__ldg(&q2b[2]);
    const float4* sq14=(const float4*)sq1;
    for(int o2=0;o2<64;o2++){
        float a=__ldg(&q1b[o2]);
        #pragma unroll
        for(int j=0;j<8;j++){
            float4 wv=sq14[o2*8+j];
            a=fmaf(wv.x,xr[4*j],a);
            a=fmaf(wv.y,xr[4*j+1],a);
            a=fmaf(wv.z,xr[4*j+2],a);
            a=fmaf(wv.w,xr[4*j+3],a);
        }
        a=gelu_f(a);
        a0=fmaf(sq2[o2],a,a0);
        a1=fmaf(sq2[64+o2],a,a1);
        a2=fmaf(sq2[128+o2],a,a2);
    }
    sout[(lane*3+0)*8+warp]=a0;
    sout[(lane*3+1)*8+warp]=a1;
    sout[(lane*3+2)*8+warp]=a2;
    __syncthreads();
    int Pb=blockIdx.x*8;
    int hwb=Pb&4095, bb=Pb>>12;
    for(int idx=threadIdx.x; idx<768; idx+=256){
        int wq=idx&7, co=(idx>>3)%3, t=idx/24;
        out[ ((size_t)(bb*32+t)*3+co)*4096 + hwb + wq ] = sout[idx];
    }
}

// ---------------- launch ----------------
extern "C" void kernel_launch(void* const* d_in, const int* in_sizes, int n_in,
                              void* d_out, int out_size){
    const float* x_t=(const float*)d_in[0];
    const float* p_w=(const float*)d_in[1];
    const float* p_b=(const float*)d_in[2];
    const float* swr=(const float*)d_in[3];
    const float* swi=(const float*)d_in[4];
    const float* pww=(const float*)d_in[5];
    const float* pwb=(const float*)d_in[6];
    const float* q1w=(const float*)d_in[7];
    const float* q1b=(const float*)d_in[8];
    const float* q2w=(const float*)d_in[9];
    const float* q2b=(const float*)d_in[10];
    float* out=(float*)d_out;

    float *b0,*b1; float2 *Z,*BY,*XF,*YF;
    cudaGetSymbolAddress((void**)&b0, g_buf0);
    cudaGetSymbolAddress((void**)&b1, g_buf1);
    cudaGetSymbolAddress((void**)&Z,  g_Z);
    cudaGetSymbolAddress((void**)&BY, g_BY);
    cudaGetSymbolAddress((void**)&XF, g_xf);
    cudaGetSymbolAddress((void**)&YF, g_yf);

    k_init_tw<<<1,256>>>();
    k_head<<<4096,256>>>(x_t,p_w,p_b,b0);

    float* cur=b0; float* nxt=b1;
    for(int l=0;l<4;l++){
        k_fwd2<<<16384,128>>>(cur,BY);
        k_fwdH<<<512,512>>>(BY,XF);
        k_mix<<<512,256>>>(swr+(size_t)l*2097152, swi+(size_t)l*2097152, XF, YF);
        k_inv2<<<2048,256>>>(YF,Z);
        k_fin<<<4096,256>>>(Z,cur,pww+(size_t)l*1024,pwb+(size_t)l*32,nxt);
        float* tmp=cur; cur=nxt; nxt=tmp;
    }
    k_tail<<<4096,256>>>(cur,q1w,q1b,q2w,q2b,out);
}